// round 12
// baseline (speedup 1.0000x reference)
#include <cuda_runtime.h>

// SparseEmbedding: out[b, :] = sum_n vals[b,n] * kernel[idx[b,n], :] + bias
// BATCH=4096, NNZ=32, VOCAB=1e6, DIM=64. float32 everywhere, idx int32.
//
// R10: single-wave + pipelined gather. R8 (8.32us, regs=80) left a 68-CTA
// straggler wave (3 CTAs/SM x 148 = 444 < 512). Capping regs at 64 via
// __launch_bounds__(256, 4) gives 4 CTAs/SM -> 592 slots -> ONE wave.
// To fit the budget, the 32-row gather is pipelined as two 16-row register
// batches (load b0 -> accumulate b0 -> load b1 -> accumulate b1), reusing
// the same 32 kv registers. Per-SM in-flight = ~28 warps x 16 loads = ~448,
// still above the per-SM queue knee, so bandwidth supply stays saturated.

#define BATCH 4096
#define NNZ   32
#define DIM   64
#define HALF  16

__global__ void __launch_bounds__(256, 4) sparse_embedding_kernel(
    const int*   __restrict__ idx,
    const float* __restrict__ vals,
    const float* __restrict__ table,
    const float* __restrict__ bias,
    float*       __restrict__ out)
{
    const int gwarp = (blockIdx.x * blockDim.x + threadIdx.x) >> 5;
    const int lane  = threadIdx.x & 31;

    // Each lane holds one (idx, val) pair for this row; broadcast via shfl.
    const int   my_idx = __ldg(idx  + gwarp * NNZ + lane);
    const float my_val = __ldg(vals + gwarp * NNZ + lane);

    float2 acc = __ldg(reinterpret_cast<const float2*>(bias) + lane);
    float2 kv[HALF];

    // Batch 0: issue 16 independent gathers, then accumulate.
#pragma unroll
    for (int n = 0; n < HALF; ++n) {
        const int id = __shfl_sync(0xffffffffu, my_idx, n);
        kv[n] = __ldcg(reinterpret_cast<const float2*>(
            table + (size_t)id * DIM) + lane);
    }
#pragma unroll
    for (int n = 0; n < HALF; ++n) {
        const float v = __shfl_sync(0xffffffffu, my_val, n);
        acc.x = fmaf(v, kv[n].x, acc.x);
        acc.y = fmaf(v, kv[n].y, acc.y);
    }

    // Batch 1: reuse the same kv registers.
#pragma unroll
    for (int n = 0; n < HALF; ++n) {
        const int id = __shfl_sync(0xffffffffu, my_idx, HALF + n);
        kv[n] = __ldcg(reinterpret_cast<const float2*>(
            table + (size_t)id * DIM) + lane);
    }
#pragma unroll
    for (int n = 0; n < HALF; ++n) {
        const float v = __shfl_sync(0xffffffffu, my_val, HALF + n);
        acc.x = fmaf(v, kv[n].x, acc.x);
        acc.y = fmaf(v, kv[n].y, acc.y);
    }

    reinterpret_cast<float2*>(out + (size_t)gwarp * DIM)[lane] = acc;
}

extern "C" void kernel_launch(void* const* d_in, const int* in_sizes, int n_in,
                              void* d_out, int out_size)
{
    const int*   idx   = (const int*)  d_in[0];
    const float* vals  = (const float*)d_in[1];
    const float* table = (const float*)d_in[2];
    const float* bias  = (const float*)d_in[3];
    float*       out   = (float*)d_out;

    // 4096 warps, 8 warps per 256-thread CTA -> 512 CTAs; with <=64 regs
    // that's 4 CTAs/SM x 148 = 592 slots -> a single resident wave.
    const int threads = 256;
    const int blocks  = (BATCH * 32) / threads;
    sparse_embedding_kernel<<<blocks, threads>>>(idx, vals, table, bias, out);
}

// round 13
// speedup vs baseline: 1.0074x; 1.0074x over previous
#include <cuda_runtime.h>

// SparseEmbedding: out[b, :] = sum_n vals[b,n] * kernel[idx[b,n], :] + bias
// BATCH=4096, NNZ=32, VOCAB=1e6, DIM=64. float32 everywhere, idx int32.
//
// R12: R8 structure verbatim (best: 8.32us; 24 warps/SM x MLP 32 = max
// in-flight product) + cache-policy tuning for cross-replay L2 retention:
//   - gathers: __ldcg  (L2-resident, no L1 lookup)
//   - idx/vals: __ldcs (streaming, evict-first -> don't displace table rows)
//   - out:      __stcs (streaming store)
// The ~31MB touched-row set fits L2 (126MB); keeping the 2MB/replay of
// streaming traffic low-priority should raise the warm-replay hit rate.

#define BATCH 4096
#define NNZ   32
#define DIM   64

__global__ void __launch_bounds__(256, 1) sparse_embedding_kernel(
    const int*   __restrict__ idx,
    const float* __restrict__ vals,
    const float* __restrict__ table,
    const float* __restrict__ bias,
    float*       __restrict__ out)
{
    const int gwarp = (blockIdx.x * blockDim.x + threadIdx.x) >> 5;
    const int lane  = threadIdx.x & 31;

    // Each lane holds one (idx, val) pair for this row; broadcast via shfl.
    // Streaming loads: idx/vals are single-use per replay -> evict first.
    const int   my_idx = __ldcs(idx  + gwarp * NNZ + lane);
    const float my_val = __ldcs(vals + gwarp * NNZ + lane);

    // Phase 1: issue ALL 32 gather loads before any consumer (MLP=32/warp).
    // .cg -> L2-direct, normal retention so rows persist across replays.
    float2 kv[NNZ];
#pragma unroll
    for (int n = 0; n < NNZ; ++n) {
        const int id = __shfl_sync(0xffffffffu, my_idx, n);
        kv[n] = __ldcg(reinterpret_cast<const float2*>(
            table + (size_t)id * DIM) + lane);
    }

    // Phase 2: accumulate (bias folded into init).
    float2 acc = __ldg(reinterpret_cast<const float2*>(bias) + lane);
#pragma unroll
    for (int n = 0; n < NNZ; ++n) {
        const float v = __shfl_sync(0xffffffffu, my_val, n);
        acc.x = fmaf(v, kv[n].x, acc.x);
        acc.y = fmaf(v, kv[n].y, acc.y);
    }

    // Streaming store: output is write-once -> don't displace table rows.
    __stcs(reinterpret_cast<float2*>(out + (size_t)gwarp * DIM) + lane, acc);
}

extern "C" void kernel_launch(void* const* d_in, const int* in_sizes, int n_in,
                              void* d_out, int out_size)
{
    const int*   idx   = (const int*)  d_in[0];
    const float* vals  = (const float*)d_in[1];
    const float* table = (const float*)d_in[2];
    const float* bias  = (const float*)d_in[3];
    float*       out   = (float*)d_out;

    // 4096 warps, 8 warps per 256-thread CTA -> 512 CTAs (R8 config).
    const int threads = 256;
    const int blocks  = (BATCH * 32) / threads;
    sparse_embedding_kernel<<<blocks, threads>>>(idx, vals, table, bias, out);
}